// round 2
// baseline (speedup 1.0000x reference)
#include <cuda_runtime.h>
#include <cuda_bf16.h>
#include <math.h>

// Problem constants
#define BATCH 4
#define SEQ   2048
#define KDIM  1024
#define HEADS 16
#define HDIM  64
#define MTOT  (BATCH*SEQ)        // 8192

// -------- scratch (device globals; allocation-free rule) ----------
__device__ float g_q[(size_t)MTOT * KDIM];
__device__ float g_k[(size_t)MTOT * KDIM];
__device__ float g_v[(size_t)MTOT * KDIM];
__device__ float g_attn[(size_t)MTOT * KDIM];

// =================================================================
// Tiled SGEMM:  C[M,N] = A[M,Kd] @ B[N,Kd]^T (+ bias)
// BM=BN=128, BK=16, 256 threads, 8x8 microtile per thread.
// =================================================================
#define BM 128
#define BN 128
#define BKT 16
#define SPAD 4  // smem row pad (keeps float4 alignment: (128+4)*4B % 16 == 0)

template<bool HAS_BIAS>
__device__ __forceinline__ void gemm_nt_tile(
    const float* __restrict__ A, const float* __restrict__ Bw,
    const float* __restrict__ bias, float* __restrict__ C,
    int Kd, int N)
{
    __shared__ float As[BKT][BM + SPAD];
    __shared__ float Bs[BKT][BN + SPAD];

    const int tid = threadIdx.x;           // 0..255
    const int tx  = tid & 15;              // 0..15
    const int ty  = tid >> 4;              // 0..15
    const int m0  = blockIdx.y * BM;
    const int n0  = blockIdx.x * BN;

    float acc[8][8];
#pragma unroll
    for (int i = 0; i < 8; i++)
#pragma unroll
        for (int j = 0; j < 8; j++) acc[i][j] = 0.f;

    for (int kt = 0; kt < Kd; kt += BKT) {
        // load A,B tiles (128 rows x 16 cols each), transposed into smem [k][m]
#pragma unroll
        for (int jj = 0; jj < 2; jj++) {
            int f   = jj * 256 + tid;      // 0..511 float4 slots
            int row = f >> 2;              // 0..127
            int c4  = (f & 3) * 4;         // 0,4,8,12
            float4 va = *(const float4*)&A [(size_t)(m0 + row) * Kd + kt + c4];
            As[c4 + 0][row] = va.x; As[c4 + 1][row] = va.y;
            As[c4 + 2][row] = va.z; As[c4 + 3][row] = va.w;
            float4 vb = *(const float4*)&Bw[(size_t)(n0 + row) * Kd + kt + c4];
            Bs[c4 + 0][row] = vb.x; Bs[c4 + 1][row] = vb.y;
            Bs[c4 + 2][row] = vb.z; Bs[c4 + 3][row] = vb.w;
        }
        __syncthreads();

#pragma unroll
        for (int k = 0; k < BKT; k++) {
            float a[8], b[8];
            *(float4*)&a[0] = *(const float4*)&As[k][ty * 8];
            *(float4*)&a[4] = *(const float4*)&As[k][ty * 8 + 4];
            *(float4*)&b[0] = *(const float4*)&Bs[k][tx * 8];
            *(float4*)&b[4] = *(const float4*)&Bs[k][tx * 8 + 4];
#pragma unroll
            for (int i = 0; i < 8; i++)
#pragma unroll
                for (int j = 0; j < 8; j++)
                    acc[i][j] = fmaf(a[i], b[j], acc[i][j]);
        }
        __syncthreads();
    }

    // epilogue
#pragma unroll
    for (int i = 0; i < 8; i++) {
        size_t rowOff = (size_t)(m0 + ty * 8 + i) * N + n0 + tx * 8;
#pragma unroll
        for (int j4 = 0; j4 < 2; j4++) {
            float4 v;
            v.x = acc[i][j4 * 4 + 0];
            v.y = acc[i][j4 * 4 + 1];
            v.z = acc[i][j4 * 4 + 2];
            v.w = acc[i][j4 * 4 + 3];
            if (HAS_BIAS) {
                const float4 bv = *(const float4*)&bias[n0 + tx * 8 + j4 * 4];
                v.x += bv.x; v.y += bv.y; v.z += bv.z; v.w += bv.w;
            }
            *(float4*)&C[rowOff + j4 * 4] = v;
        }
    }
}

// grid (8, 64, 3): z selects Q/K/V
__global__ void __launch_bounds__(256, 2)
qkv_kernel(const float* __restrict__ x,
           const float* __restrict__ Wq,
           const float* __restrict__ Wk,
           const float* __restrict__ Wv)
{
    const float* W;
    float* C;
    if (blockIdx.z == 0)      { W = Wq; C = g_q; }
    else if (blockIdx.z == 1) { W = Wk; C = g_k; }
    else                      { W = Wv; C = g_v; }
    gemm_nt_tile<false>(x, W, nullptr, C, KDIM, KDIM);
}

__global__ void __launch_bounds__(256, 2)
out_proj_kernel(const float* __restrict__ Wu,
                const float* __restrict__ bu,
                float* __restrict__ out)
{
    gemm_nt_tile<true>(g_attn, Wu, bu, out, KDIM, KDIM);
}

// =================================================================
// Flash attention, fp32. Block = 64 query rows of one (b,h).
// 256 threads as 16x16; each thread owns 4 rows x 4 cols.
// =================================================================
#define APAD 4
#define AROW (HDIM + APAD)     // 68
#define SMEM_ATTN (4 * HDIM * AROW * (int)sizeof(float))   // 69632 B

#define F4C(v, j) ((j) == 0 ? (v).x : (j) == 1 ? (v).y : (j) == 2 ? (v).z : (v).w)

__global__ void __launch_bounds__(256, 3)
attn_kernel()
{
    extern __shared__ float sm[];
    float* Qs  = sm;                       // [64][68]  (rows x d), pre-scaled
    float* Kts = Qs  + HDIM * AROW;        // [d][key]
    float* Vs  = Kts + HDIM * AROW;        // [key][d]
    float* Ps  = Vs  + HDIM * AROW;        // [row][key]

    const int tid = threadIdx.x;
    const int tx  = tid & 15;              // col group
    const int ty  = tid >> 4;              // row group
    const int r0  = ty * 4;
    const int c0  = tx * 4;

    const int qb = blockIdx.x;             // 0..31 query tile
    const int bh = blockIdx.y;             // 0..63
    const int b  = bh >> 4;
    const int h  = bh & 15;

    const float* qbase = g_q + (size_t)b * SEQ * KDIM + (size_t)h * HDIM;
    const float* kbase = g_k + (size_t)b * SEQ * KDIM + (size_t)h * HDIM;
    const float* vbase = g_v + (size_t)b * SEQ * KDIM + (size_t)h * HDIM;

    const float scale = 0.03125f;          // 1/sqrt(1024)

    // load Q tile, pre-scaled
#pragma unroll
    for (int j = 0; j < 4; j++) {
        int f   = j * 256 + tid;           // 0..1023
        int row = f >> 4;                  // 0..63
        int d0  = (f & 15) * 4;
        float4 v = *(const float4*)&qbase[(size_t)(qb * 64 + row) * KDIM + d0];
        v.x *= scale; v.y *= scale; v.z *= scale; v.w *= scale;
        *(float4*)&Qs[row * AROW + d0] = v;
    }

    float m[4], l[4], o[4][4];
#pragma unroll
    for (int i = 0; i < 4; i++) {
        m[i] = -3.0e38f; l[i] = 0.f;
#pragma unroll
        for (int j = 0; j < 4; j++) o[i][j] = 0.f;
    }

    for (int kt = 0; kt < SEQ / 64; kt++) {
        __syncthreads();  // protects Qs (iter 0) and Kts/Vs/Ps reuse (iters > 0)

        // load K tile transposed [d][key], V tile direct [key][d]
#pragma unroll
        for (int j = 0; j < 4; j++) {
            int f   = j * 256 + tid;
            int row = f >> 4;              // key index 0..63
            int d0  = (f & 15) * 4;
            float4 kv = *(const float4*)&kbase[(size_t)(kt * 64 + row) * KDIM + d0];
            Kts[(d0 + 0) * AROW + row] = kv.x;
            Kts[(d0 + 1) * AROW + row] = kv.y;
            Kts[(d0 + 2) * AROW + row] = kv.z;
            Kts[(d0 + 3) * AROW + row] = kv.w;
            float4 vv = *(const float4*)&vbase[(size_t)(kt * 64 + row) * KDIM + d0];
            *(float4*)&Vs[row * AROW + d0] = vv;
        }
        __syncthreads();

        // S = Q @ K^T  (already scaled)
        float s[4][4];
#pragma unroll
        for (int i = 0; i < 4; i++)
#pragma unroll
            for (int j = 0; j < 4; j++) s[i][j] = 0.f;

#pragma unroll
        for (int d = 0; d < HDIM; d += 4) {
            float4 qv[4];
#pragma unroll
            for (int i = 0; i < 4; i++)
                qv[i] = *(const float4*)&Qs[(r0 + i) * AROW + d];
            float4 k0 = *(const float4*)&Kts[(d + 0) * AROW + c0];
            float4 k1 = *(const float4*)&Kts[(d + 1) * AROW + c0];
            float4 k2 = *(const float4*)&Kts[(d + 2) * AROW + c0];
            float4 k3 = *(const float4*)&Kts[(d + 3) * AROW + c0];
#pragma unroll
            for (int i = 0; i < 4; i++)
#pragma unroll
                for (int j = 0; j < 4; j++) {
                    s[i][j] = fmaf(F4C(qv[i], 0), F4C(k0, j), s[i][j]);
                    s[i][j] = fmaf(F4C(qv[i], 1), F4C(k1, j), s[i][j]);
                    s[i][j] = fmaf(F4C(qv[i], 2), F4C(k2, j), s[i][j]);
                    s[i][j] = fmaf(F4C(qv[i], 3), F4C(k3, j), s[i][j]);
                }
        }

        // online softmax per row (16-lane reduction across tx)
#pragma unroll
        for (int i = 0; i < 4; i++) {
            float rm = fmaxf(fmaxf(s[i][0], s[i][1]), fmaxf(s[i][2], s[i][3]));
#pragma unroll
            for (int off = 8; off > 0; off >>= 1)
                rm = fmaxf(rm, __shfl_xor_sync(0xffffffffu, rm, off, 16));
            float nm = fmaxf(m[i], rm);
            float al = __expf(m[i] - nm);
            m[i] = nm;
            float ps = 0.f;
#pragma unroll
            for (int j = 0; j < 4; j++) {
                s[i][j] = __expf(s[i][j] - nm);
                ps += s[i][j];
            }
#pragma unroll
            for (int off = 8; off > 0; off >>= 1)
                ps += __shfl_xor_sync(0xffffffffu, ps, off, 16);
            l[i] = l[i] * al + ps;
#pragma unroll
            for (int j = 0; j < 4; j++) o[i][j] *= al;
            *(float4*)&Ps[(r0 + i) * AROW + c0] =
                make_float4(s[i][0], s[i][1], s[i][2], s[i][3]);
        }
        __syncthreads();

        // O += P @ V
#pragma unroll
        for (int jj = 0; jj < 64; jj += 4) {
            float4 pv[4];
#pragma unroll
            for (int i = 0; i < 4; i++)
                pv[i] = *(const float4*)&Ps[(r0 + i) * AROW + jj];
            float4 v0 = *(const float4*)&Vs[(jj + 0) * AROW + c0];
            float4 v1 = *(const float4*)&Vs[(jj + 1) * AROW + c0];
            float4 v2 = *(const float4*)&Vs[(jj + 2) * AROW + c0];
            float4 v3 = *(const float4*)&Vs[(jj + 3) * AROW + c0];
#pragma unroll
            for (int i = 0; i < 4; i++)
#pragma unroll
                for (int c = 0; c < 4; c++) {
                    o[i][c] = fmaf(F4C(pv[i], 0), F4C(v0, c), o[i][c]);
                    o[i][c] = fmaf(F4C(pv[i], 1), F4C(v1, c), o[i][c]);
                    o[i][c] = fmaf(F4C(pv[i], 2), F4C(v2, c), o[i][c]);
                    o[i][c] = fmaf(F4C(pv[i], 3), F4C(v3, c), o[i][c]);
                }
        }
    }

    // normalize + store to g_attn in [B,T,K] layout
#pragma unroll
    for (int i = 0; i < 4; i++) {
        float inv = 1.f / l[i];
        float4 v = make_float4(o[i][0] * inv, o[i][1] * inv,
                               o[i][2] * inv, o[i][3] * inv);
        *(float4*)&g_attn[(size_t)(b * SEQ + qb * 64 + r0 + i) * KDIM +
                          (size_t)h * HDIM + c0] = v;
    }
}

// =================================================================
extern "C" void kernel_launch(void* const* d_in, const int* in_sizes, int n_in,
                              void* d_out, int out_size)
{
    const float* x  = (const float*)d_in[0];
    const float* Wk = (const float*)d_in[1];
    const float* Wq = (const float*)d_in[2];
    const float* Wv = (const float*)d_in[3];
    const float* Wu = (const float*)d_in[4];
    const float* bu = (const float*)d_in[5];
    float* out = (float*)d_out;

    // One-time (host-side, idempotent): raise attn kernel's dynamic smem cap.
    static bool attr_done = false;
    if (!attr_done) {
        cudaFuncSetAttribute(attn_kernel,
                             cudaFuncAttributeMaxDynamicSharedMemorySize,
                             SMEM_ATTN);
        attr_done = true;
    }

    // QKV projections: grid (N/128, M/128, 3)
    qkv_kernel<<<dim3(KDIM / BN, MTOT / BM, 3), 256>>>(x, Wq, Wk, Wv);

    // attention
    attn_kernel<<<dim3(SEQ / 64, BATCH * HEADS), 256, SMEM_ATTN>>>();

    // output projection
    out_proj_kernel<<<dim3(KDIM / BN, MTOT / BM), 256>>>(Wu, bu, out);
}

// round 9
// speedup vs baseline: 1.3185x; 1.3185x over previous
#include <cuda_runtime.h>
#include <cuda_bf16.h>
#include <math.h>
#include <stdint.h>

// Problem constants
#define BATCH 4
#define SEQ   2048
#define KDIM  1024
#define HEADS 16
#define HDIM  64
#define MTOT  (BATCH*SEQ)        // 8192

// -------- scratch (device globals; allocation-free rule) ----------
__device__ float g_q[(size_t)MTOT * KDIM];
__device__ float g_k[(size_t)MTOT * KDIM];
__device__ float g_v[(size_t)MTOT * KDIM];
__device__ float g_attn[(size_t)MTOT * KDIM];

// bf16 hi/lo split scratch
__device__ __nv_bfloat16 g_xhi[(size_t)MTOT * KDIM];
__device__ __nv_bfloat16 g_xlo[(size_t)MTOT * KDIM];
__device__ __nv_bfloat16 g_ahi[(size_t)MTOT * KDIM];
__device__ __nv_bfloat16 g_alo[(size_t)MTOT * KDIM];
__device__ __nv_bfloat16 g_wqhi[(size_t)KDIM * KDIM];
__device__ __nv_bfloat16 g_wqlo[(size_t)KDIM * KDIM];
__device__ __nv_bfloat16 g_wkhi[(size_t)KDIM * KDIM];
__device__ __nv_bfloat16 g_wklo[(size_t)KDIM * KDIM];
__device__ __nv_bfloat16 g_wvhi[(size_t)KDIM * KDIM];
__device__ __nv_bfloat16 g_wvlo[(size_t)KDIM * KDIM];
__device__ __nv_bfloat16 g_wuhi[(size_t)KDIM * KDIM];
__device__ __nv_bfloat16 g_wulo[(size_t)KDIM * KDIM];

// =================================================================
// Helpers: cp.async, ldmatrix, mma.sync (all base sm_80+ features,
// legal on compute_103 non-'a' target), packed f32x2 (sm_100+ base).
// =================================================================
__device__ __forceinline__ uint32_t s2u(const void* p) {
    return (uint32_t)__cvta_generic_to_shared(p);
}
__device__ __forceinline__ void cp16(uint32_t dst, const void* src) {
    asm volatile("cp.async.cg.shared.global [%0], [%1], 16;"
                 :: "r"(dst), "l"(src));
}
__device__ __forceinline__ void ldsm_x4(uint32_t& r0, uint32_t& r1,
                                        uint32_t& r2, uint32_t& r3,
                                        uint32_t addr) {
    asm volatile("ldmatrix.sync.aligned.m8n8.x4.shared.b16 {%0,%1,%2,%3}, [%4];"
                 : "=r"(r0), "=r"(r1), "=r"(r2), "=r"(r3) : "r"(addr));
}
__device__ __forceinline__ void mma16816(float* d, const uint32_t* a,
                                         const uint32_t* b, const float* c) {
    asm volatile(
        "mma.sync.aligned.m16n8k16.row.col.f32.bf16.bf16.f32 "
        "{%0,%1,%2,%3}, {%4,%5,%6,%7}, {%8,%9}, {%10,%11,%12,%13};"
        : "=f"(d[0]), "=f"(d[1]), "=f"(d[2]), "=f"(d[3])
        : "r"(a[0]), "r"(a[1]), "r"(a[2]), "r"(a[3]),
          "r"(b[0]), "r"(b[1]),
          "f"(c[0]), "f"(c[1]), "f"(c[2]), "f"(c[3]));
}

// packed f32x2 (FFMA2) helpers — compile-verified OK on sm_103 in R8
__device__ __forceinline__ unsigned long long pk2(float x, float y) {
    unsigned long long r;
    asm("mov.b64 %0, {%1, %2};" : "=l"(r) : "f"(x), "f"(y));
    return r;
}
__device__ __forceinline__ void upk2(unsigned long long v, float& x, float& y) {
    asm("mov.b64 {%0, %1}, %2;" : "=f"(x), "=f"(y) : "l"(v));
}
__device__ __forceinline__ unsigned long long ffma2(
    unsigned long long a, unsigned long long b, unsigned long long c) {
    unsigned long long d;
    asm("fma.rn.f32x2 %0, %1, %2, %3;" : "=l"(d) : "l"(a), "l"(b), "l"(c));
    return d;
}
__device__ __forceinline__ unsigned long long fmul2(
    unsigned long long a, unsigned long long b) {
    unsigned long long d;
    asm("mul.rn.f32x2 %0, %1, %2;" : "=l"(d) : "l"(a), "l"(b));
    return d;
}

// =================================================================
// Split fp32 -> bf16 hi + bf16 lo (Markidis). which selects dst (and
// optionally src = g_attn for which==5).
// =================================================================
__global__ void split_kernel(const float* __restrict__ src, int which, int n4)
{
    int i = blockIdx.x * blockDim.x + threadIdx.x;
    if (i >= n4) return;
    __nv_bfloat16 *hi, *lo;
    switch (which) {
        case 0: hi = g_xhi;  lo = g_xlo;  break;
        case 1: hi = g_wqhi; lo = g_wqlo; break;
        case 2: hi = g_wkhi; lo = g_wklo; break;
        case 3: hi = g_wvhi; lo = g_wvlo; break;
        case 4: hi = g_wuhi; lo = g_wulo; break;
        default: hi = g_ahi; lo = g_alo; src = g_attn; break;
    }
    float4 v = ((const float4*)src)[i];
    __nv_bfloat16 h0 = __float2bfloat16(v.x);
    __nv_bfloat16 h1 = __float2bfloat16(v.y);
    __nv_bfloat16 h2 = __float2bfloat16(v.z);
    __nv_bfloat16 h3 = __float2bfloat16(v.w);
    __nv_bfloat16 l0 = __float2bfloat16(v.x - __bfloat162float(h0));
    __nv_bfloat16 l1 = __float2bfloat16(v.y - __bfloat162float(h1));
    __nv_bfloat16 l2 = __float2bfloat16(v.z - __bfloat162float(h2));
    __nv_bfloat16 l3 = __float2bfloat16(v.w - __bfloat162float(h3));
    __nv_bfloat162* hp = (__nv_bfloat162*)hi;
    __nv_bfloat162* lp = (__nv_bfloat162*)lo;
    hp[2*i]   = __halves2bfloat162(h0, h1);
    hp[2*i+1] = __halves2bfloat162(h2, h3);
    lp[2*i]   = __halves2bfloat162(l0, l1);
    lp[2*i+1] = __halves2bfloat162(l2, l3);
}

// =================================================================
// HMMA bf16-split GEMM:  C[M,N] = A[M,1024] @ B[N,1024]^T (+bias)
// mma.sync.m16n8k16. Block tile 128x128, 8 warps @ 32x64,
// K chunks of 32 double-buffered via cp.async.
// 3 terms: Ahi*Bhi + Ahi*Blo + Alo*Bhi, fp32 accumulators.
// Smem rows padded to 40 bf16 (80B): ldmatrix bank-conflict-free.
// =================================================================
#define BM 128
#define BN 128
#define BKC 32
#define TROW 40                           // padded row stride (bf16)
#define TILE_BYTES (128 * TROW * 2)       // 10240
#define STAGE_BYTES (4 * TILE_BYTES)      // 40960 (Ahi,Alo,Bhi,Blo)
#define GEMM_SMEM (2 * STAGE_BYTES)       // 81920

template<bool HAS_BIAS>
__device__ __forceinline__ void gemm_mma_body(
    const __nv_bfloat16* __restrict__ Ahi, const __nv_bfloat16* __restrict__ Alo,
    const __nv_bfloat16* __restrict__ Bhi, const __nv_bfloat16* __restrict__ Blo,
    const float* __restrict__ bias, float* __restrict__ C)
{
    extern __shared__ char smc[];
    const uint32_t sbase = s2u(smc);
    const int tid    = threadIdx.x;
    const int wid    = tid >> 5;
    const int lane   = tid & 31;
    const int warp_m = wid & 3;          // 4 warps along M (32 rows each)
    const int warp_n = wid >> 2;         // 2 warps along N (64 cols each)
    const int m0 = blockIdx.y * BM;
    const int n0 = blockIdx.x * BN;

    const __nv_bfloat16* gsrc[4] = {
        Ahi + (size_t)m0 * KDIM, Alo + (size_t)m0 * KDIM,
        Bhi + (size_t)n0 * KDIM, Blo + (size_t)n0 * KDIM
    };

    float acc[2][8][4];
#pragma unroll
    for (int a = 0; a < 2; a++)
#pragma unroll
        for (int b = 0; b < 8; b++)
#pragma unroll
            for (int c = 0; c < 4; c++) acc[a][b][c] = 0.f;

    // loader: 4 tiles x 128 rows x 32 bf16 (4x16B per row)
    auto load_chunk = [&](int kt, int stage) {
        const uint32_t sb = sbase + stage * STAGE_BYTES;
#pragma unroll
        for (int t = 0; t < 4; t++) {
            const __nv_bfloat16* g = gsrc[t] + kt * BKC;
#pragma unroll
            for (int i = 0; i < 2; i++) {
                int idx = i * 256 + tid;          // 0..511
                int row = idx >> 2;               // 0..127
                int c   = idx & 3;                // 16B chunk in row
                cp16(sb + t * TILE_BYTES + row * (TROW * 2) + c * 16,
                     g + (size_t)row * KDIM + c * 8);
            }
        }
        asm volatile("cp.async.commit_group;" ::: "memory");
    };

    load_chunk(0, 0);

    const int NC = KDIM / BKC;   // 32
    for (int kc = 0; kc < NC; kc++) {
        if (kc + 1 < NC) {
            load_chunk(kc + 1, (kc + 1) & 1);
            asm volatile("cp.async.wait_group 1;" ::: "memory");
        } else {
            asm volatile("cp.async.wait_group 0;" ::: "memory");
        }
        __syncthreads();

        const uint32_t sb   = sbase + (kc & 1) * STAGE_BYTES;
        const uint32_t aHiB = sb;
        const uint32_t aLoB = sb + TILE_BYTES;
        const uint32_t bHiB = sb + 2 * TILE_BYTES;
        const uint32_t bLoB = sb + 3 * TILE_BYTES;

#pragma unroll
        for (int kk = 0; kk < 2; kk++) {           // two k16 steps
            // --- A fragments (m16k16 via ldmatrix.x4) ---
            uint32_t ah[2][4], al[2][4];
            const int arow  = warp_m * 32 + (lane & 15);
            const int akofs = kk * 16 + ((lane & 16) ? 8 : 0);
#pragma unroll
            for (int fm = 0; fm < 2; fm++) {
                uint32_t off = (uint32_t)((arow + fm * 16) * TROW + akofs) * 2;
                ldsm_x4(ah[fm][0], ah[fm][1], ah[fm][2], ah[fm][3], aHiB + off);
                ldsm_x4(al[fm][0], al[fm][1], al[fm][2], al[fm][3], aLoB + off);
            }
            // --- B fragments (two n8 frags per ldmatrix.x4) ---
            uint32_t bh[8][2], bl[8][2];
            const int brow_l = (lane & 7) + ((lane & 16) ? 8 : 0);
            const int bkofs  = kk * 16 + ((lane & 8) ? 8 : 0);
#pragma unroll
            for (int j = 0; j < 4; j++) {
                uint32_t off = (uint32_t)((warp_n * 64 + j * 16 + brow_l) * TROW
                                          + bkofs) * 2;
                uint32_t r0, r1, r2, r3;
                ldsm_x4(r0, r1, r2, r3, bHiB + off);
                bh[2*j][0] = r0; bh[2*j][1] = r1;
                bh[2*j+1][0] = r2; bh[2*j+1][1] = r3;
                ldsm_x4(r0, r1, r2, r3, bLoB + off);
                bl[2*j][0] = r0; bl[2*j][1] = r1;
                bl[2*j+1][0] = r2; bl[2*j+1][1] = r3;
            }
            // --- 3-term HMMA ---
#pragma unroll
            for (int fm = 0; fm < 2; fm++)
#pragma unroll
                for (int fn = 0; fn < 8; fn++) {
                    mma16816(acc[fm][fn], ah[fm], bh[fn], acc[fm][fn]);
                    mma16816(acc[fm][fn], ah[fm], bl[fn], acc[fm][fn]);
                    mma16816(acc[fm][fn], al[fm], bh[fn], acc[fm][fn]);
                }
        }
        __syncthreads();
    }

    // ---- epilogue: fragment -> gmem (float2 stores) ----
#pragma unroll
    for (int fm = 0; fm < 2; fm++) {
        int row0 = m0 + warp_m * 32 + fm * 16 + (lane >> 2);
#pragma unroll
        for (int fn = 0; fn < 8; fn++) {
            int col = n0 + warp_n * 64 + fn * 8 + (lane & 3) * 2;
            float b0 = 0.f, b1 = 0.f;
            if (HAS_BIAS) { b0 = bias[col]; b1 = bias[col + 1]; }
            float2 v0 = make_float2(acc[fm][fn][0] + b0, acc[fm][fn][1] + b1);
            float2 v1 = make_float2(acc[fm][fn][2] + b0, acc[fm][fn][3] + b1);
            *(float2*)&C[(size_t)row0 * KDIM + col]       = v0;
            *(float2*)&C[(size_t)(row0 + 8) * KDIM + col] = v1;
        }
    }
}

// grid (8, 64, 3): z selects Q/K/V
__global__ void __launch_bounds__(256, 1)
qkv_tc_kernel()
{
    const __nv_bfloat16 *bh, *bl;
    float* C;
    if (blockIdx.z == 0)      { bh = g_wqhi; bl = g_wqlo; C = g_q; }
    else if (blockIdx.z == 1) { bh = g_wkhi; bl = g_wklo; C = g_k; }
    else                      { bh = g_wvhi; bl = g_wvlo; C = g_v; }
    gemm_mma_body<false>(g_xhi, g_xlo, bh, bl, nullptr, C);
}

__global__ void __launch_bounds__(256, 1)
out_tc_kernel(const float* __restrict__ bu, float* __restrict__ out)
{
    gemm_mma_body<true>(g_ahi, g_alo, g_wuhi, g_wulo, bu, out);
}

// =================================================================
// Flash attention, fp32 with packed f32x2 (FFMA2) inner loops.
// Block = 64 query rows of one (b,h). 256 threads as 16x16;
// each thread owns 4 rows x 4 cols.
// =================================================================
#define APAD 4
#define AROW (HDIM + APAD)     // 68
#define SMEM_ATTN (4 * HDIM * AROW * (int)sizeof(float))   // 69632 B

__global__ void __launch_bounds__(256, 3)
attn_kernel()
{
    extern __shared__ float smf[];
    float* Qs  = smf;
    float* Kts = Qs  + HDIM * AROW;
    float* Vs  = Kts + HDIM * AROW;
    float* Ps  = Vs  + HDIM * AROW;

    const int tid = threadIdx.x;
    const int tx  = tid & 15;
    const int ty  = tid >> 4;
    const int r0  = ty * 4;
    const int c0  = tx * 4;

    const int qb = blockIdx.x;
    const int bh = blockIdx.y;
    const int b  = bh >> 4;
    const int h  = bh & 15;

    const float* qbase = g_q + (size_t)b * SEQ * KDIM + (size_t)h * HDIM;
    const float* kbase = g_k + (size_t)b * SEQ * KDIM + (size_t)h * HDIM;
    const float* vbase = g_v + (size_t)b * SEQ * KDIM + (size_t)h * HDIM;

    const float scale = 0.03125f;

#pragma unroll
    for (int j = 0; j < 4; j++) {
        int f   = j * 256 + tid;
        int row = f >> 4;
        int d0  = (f & 15) * 4;
        float4 v = *(const float4*)&qbase[(size_t)(qb * 64 + row) * KDIM + d0];
        v.x *= scale; v.y *= scale; v.z *= scale; v.w *= scale;
        *(float4*)&Qs[row * AROW + d0] = v;
    }

    float m[4], l[4];
    unsigned long long o01[4], o23[4];
#pragma unroll
    for (int i = 0; i < 4; i++) {
        m[i] = -3.0e38f; l[i] = 0.f;
        o01[i] = 0ull; o23[i] = 0ull;
    }

    for (int kt = 0; kt < SEQ / 64; kt++) {
        __syncthreads();
#pragma unroll
        for (int j = 0; j < 4; j++) {
            int f   = j * 256 + tid;
            int row = f >> 4;
            int d0  = (f & 15) * 4;
            float4 kv = *(const float4*)&kbase[(size_t)(kt * 64 + row) * KDIM + d0];
            Kts[(d0 + 0) * AROW + row] = kv.x;
            Kts[(d0 + 1) * AROW + row] = kv.y;
            Kts[(d0 + 2) * AROW + row] = kv.z;
            Kts[(d0 + 3) * AROW + row] = kv.w;
            float4 vv = *(const float4*)&vbase[(size_t)(kt * 64 + row) * KDIM + d0];
            *(float4*)&Vs[row * AROW + d0] = vv;
        }
        __syncthreads();

        unsigned long long s01[4], s23[4];
#pragma unroll
        for (int i = 0; i < 4; i++) { s01[i] = 0ull; s23[i] = 0ull; }

#pragma unroll
        for (int d = 0; d < HDIM; d += 4) {
            float4 qv[4];
#pragma unroll
            for (int i = 0; i < 4; i++)
                qv[i] = *(const float4*)&Qs[(r0 + i) * AROW + d];
            float4 k0 = *(const float4*)&Kts[(d + 0) * AROW + c0];
            float4 k1 = *(const float4*)&Kts[(d + 1) * AROW + c0];
            float4 k2 = *(const float4*)&Kts[(d + 2) * AROW + c0];
            float4 k3 = *(const float4*)&Kts[(d + 3) * AROW + c0];
            unsigned long long k0a = pk2(k0.x, k0.y), k0b = pk2(k0.z, k0.w);
            unsigned long long k1a = pk2(k1.x, k1.y), k1b = pk2(k1.z, k1.w);
            unsigned long long k2a = pk2(k2.x, k2.y), k2b = pk2(k2.z, k2.w);
            unsigned long long k3a = pk2(k3.x, k3.y), k3b = pk2(k3.z, k3.w);
#pragma unroll
            for (int i = 0; i < 4; i++) {
                unsigned long long q;
                q = pk2(qv[i].x, qv[i].x);
                s01[i] = ffma2(q, k0a, s01[i]); s23[i] = ffma2(q, k0b, s23[i]);
                q = pk2(qv[i].y, qv[i].y);
                s01[i] = ffma2(q, k1a, s01[i]); s23[i] = ffma2(q, k1b, s23[i]);
                q = pk2(qv[i].z, qv[i].z);
                s01[i] = ffma2(q, k2a, s01[i]); s23[i] = ffma2(q, k2b, s23[i]);
                q = pk2(qv[i].w, qv[i].w);
                s01[i] = ffma2(q, k3a, s01[i]); s23[i] = ffma2(q, k3b, s23[i]);
            }
        }

#pragma unroll
        for (int i = 0; i < 4; i++) {
            float s0, s1, s2, s3;
            upk2(s01[i], s0, s1);
            upk2(s23[i], s2, s3);
            float rm = fmaxf(fmaxf(s0, s1), fmaxf(s2, s3));
#pragma unroll
            for (int off = 8; off > 0; off >>= 1)
                rm = fmaxf(rm, __shfl_xor_sync(0xffffffffu, rm, off, 16));
            float nm = fmaxf(m[i], rm);
            float al = __expf(m[i] - nm);
            m[i] = nm;
            s0 = __expf(s0 - nm); s1 = __expf(s1 - nm);
            s2 = __expf(s2 - nm); s3 = __expf(s3 - nm);
            float ps = s0 + s1 + s2 + s3;
#pragma unroll
            for (int off = 8; off > 0; off >>= 1)
                ps += __shfl_xor_sync(0xffffffffu, ps, off, 16);
            l[i] = l[i] * al + ps;
            unsigned long long alp = pk2(al, al);
            o01[i] = fmul2(alp, o01[i]);
            o23[i] = fmul2(alp, o23[i]);
            *(float4*)&Ps[(r0 + i) * AROW + c0] = make_float4(s0, s1, s2, s3);
        }
        __syncthreads();

#pragma unroll
        for (int jj = 0; jj < 64; jj += 4) {
            float4 pv[4];
#pragma unroll
            for (int i = 0; i < 4; i++)
                pv[i] = *(const float4*)&Ps[(r0 + i) * AROW + jj];
            float4 v0 = *(const float4*)&Vs[(jj + 0) * AROW + c0];
            float4 v1 = *(const float4*)&Vs[(jj + 1) * AROW + c0];
            float4 v2 = *(const float4*)&Vs[(jj + 2) * AROW + c0];
            float4 v3 = *(const float4*)&Vs[(jj + 3) * AROW + c0];
            unsigned long long v0a = pk2(v0.x, v0.y), v0b = pk2(v0.z, v0.w);
            unsigned long long v1a = pk2(v1.x, v1.y), v1b = pk2(v1.z, v1.w);
            unsigned long long v2a = pk2(v2.x, v2.y), v2b = pk2(v2.z, v2.w);
            unsigned long long v3a = pk2(v3.x, v3.y), v3b = pk2(v3.z, v3.w);
#pragma unroll
            for (int i = 0; i < 4; i++) {
                unsigned long long p;
                p = pk2(pv[i].x, pv[i].x);
                o01[i] = ffma2(p, v0a, o01[i]); o23[i] = ffma2(p, v0b, o23[i]);
                p = pk2(pv[i].y, pv[i].y);
                o01[i] = ffma2(p, v1a, o01[i]); o23[i] = ffma2(p, v1b, o23[i]);
                p = pk2(pv[i].z, pv[i].z);
                o01[i] = ffma2(p, v2a, o01[i]); o23[i] = ffma2(p, v2b, o23[i]);
                p = pk2(pv[i].w, pv[i].w);
                o01[i] = ffma2(p, v3a, o01[i]); o23[i] = ffma2(p, v3b, o23[i]);
            }
        }
    }

#pragma unroll
    for (int i = 0; i < 4; i++) {
        float inv = 1.f / l[i];
        float o0, o1, o2, o3;
        upk2(o01[i], o0, o1);
        upk2(o23[i], o2, o3);
        float4 v = make_float4(o0 * inv, o1 * inv, o2 * inv, o3 * inv);
        *(float4*)&g_attn[(size_t)(b * SEQ + qb * 64 + r0 + i) * KDIM +
                          (size_t)h * HDIM + c0] = v;
    }
}

// =================================================================
extern "C" void kernel_launch(void* const* d_in, const int* in_sizes, int n_in,
                              void* d_out, int out_size)
{
    const float* x  = (const float*)d_in[0];
    const float* Wk = (const float*)d_in[1];
    const float* Wq = (const float*)d_in[2];
    const float* Wv = (const float*)d_in[3];
    const float* Wu = (const float*)d_in[4];
    const float* bu = (const float*)d_in[5];
    float* out = (float*)d_out;

    static bool attr_done = false;
    if (!attr_done) {
        cudaFuncSetAttribute(attn_kernel,
                             cudaFuncAttributeMaxDynamicSharedMemorySize, SMEM_ATTN);
        cudaFuncSetAttribute(qkv_tc_kernel,
                             cudaFuncAttributeMaxDynamicSharedMemorySize, GEMM_SMEM);
        cudaFuncSetAttribute(out_tc_kernel,
                             cudaFuncAttributeMaxDynamicSharedMemorySize, GEMM_SMEM);
        attr_done = true;
    }

    const int n4x = MTOT * KDIM / 4;   // 2,097,152
    const int n4w = KDIM * KDIM / 4;   //   262,144

    // hi/lo splits of x and weights
    split_kernel<<<n4x / 256, 256>>>(x,  0, n4x);
    split_kernel<<<n4w / 256, 256>>>(Wq, 1, n4w);
    split_kernel<<<n4w / 256, 256>>>(Wk, 2, n4w);
    split_kernel<<<n4w / 256, 256>>>(Wv, 3, n4w);
    split_kernel<<<n4w / 256, 256>>>(Wu, 4, n4w);

    // QKV projections on tensor cores (HMMA)
    qkv_tc_kernel<<<dim3(KDIM / BN, MTOT / BM, 3), 256, GEMM_SMEM>>>();

    // attention (fp32 flash, FFMA2 inner loops)
    attn_kernel<<<dim3(SEQ / 64, BATCH * HEADS), 256, SMEM_ATTN>>>();

    // split attention output, then output projection on tensor cores
    split_kernel<<<n4x / 256, 256>>>(nullptr, 5, n4x);
    out_tc_kernel<<<dim3(KDIM / BN, MTOT / BM), 256, GEMM_SMEM>>>(bu, out);
}